// round 1
// baseline (speedup 1.0000x reference)
#include <cuda_runtime.h>

#define HH 180
#define WW 180
#define BB 8
#define NF 24
#define IMG (HH*WW)            // 32400
#define TOT (BB*IMG)           // 259200

#define TX 32
#define TY 16
#define SW (TX+4)              // 36  S-region width
#define SH (TY+4)              // 20  S-region height
#define UW (TX+8)              // 40  u-region width
#define UH (TY+8)              // 24  u-region height
#define NSP (SW*SH)            // 720
#define NUP (UW*UH)            // 960

#define LUTN 8192              // intervals
#define LUTE (LUTN+1)          // entries
#define XMIN (-2.0f)
#define LUT_SCALE 2048.0f      // LUTN/4

__device__ float g_lut[LUTE + 8];
__device__ float g_part[256];
__device__ float g_invM[1];

// ---------------------------------------------------------------- LUT build
__global__ void lut_kernel(const float* __restrict__ mu,
                           const float* __restrict__ w) {
    int i = blockIdx.x * blockDim.x + threadIdx.x;
    if (i < LUTE) {
        float x = XMIN + (float)i * (4.0f / (float)LUTN);
        float s = 0.0f;
        #pragma unroll 1
        for (int j = 0; j < 31; j++) {
            float d = x - mu[j];
            s += w[j] * expf(-d * d * 50.0f);   // 1/(2*0.1^2) = 50
        }
        g_lut[i] = s;
    }
}

// ------------------------------------------------- deterministic M reduction
// sum(u_sigma) = sum_q u[q] * cy(q)*cx(q) / 9   (count_include_pad avg pool)
__global__ void red1_kernel(const float* __restrict__ u) {
    __shared__ float red[256];
    int tid = threadIdx.x;
    float s = 0.0f;
    for (int i = blockIdx.x * 256 + tid; i < TOT; i += 256 * 256) {
        int pix = i % IMG;
        int y = pix / WW;
        int x = pix - y * WW;
        float cy = (y == 0 || y == HH - 1) ? 2.0f : 3.0f;
        float cx = (x == 0 || x == WW - 1) ? 2.0f : 3.0f;
        s += u[i] * (cy * cx);
    }
    red[tid] = s;
    __syncthreads();
    #pragma unroll
    for (int st = 128; st > 0; st >>= 1) {
        if (tid < st) red[tid] += red[tid + st];
        __syncthreads();
    }
    if (tid == 0) g_part[blockIdx.x] = red[0];
}

__global__ void red2_kernel() {
    __shared__ float red[256];
    int tid = threadIdx.x;
    red[tid] = g_part[tid];
    __syncthreads();
    #pragma unroll
    for (int st = 128; st > 0; st >>= 1) {
        if (tid < st) red[tid] += red[tid + st];
        __syncthreads();
    }
    if (tid == 0) {
        float M = red[0] / (9.0f * (float)TOT) + 0.001f;
        g_invM[0] = 1.0f / M;
    }
}

// ----------------------------------------------------------- fused main pass
__global__ __launch_bounds__(512, 2)
void tnrd_kernel(const float* __restrict__ u,
                 const float* __restrict__ f,
                 const float* __restrict__ filters,
                 const float* __restrict__ lam_p,
                 float* __restrict__ out) {
    __shared__ float su[NUP];          // u tile with halo 4
    __shared__ float susig[NSP];       // u_sigma on S-region (halo 2)
    __shared__ float sS[NSP];          // current filter's scaled_phi (no /M)
    __shared__ float sfilt[NF * 25];
    __shared__ float slut[LUTE + 1];

    const int tid = threadIdx.x;
    const int x0 = blockIdx.x * TX;
    const int y0 = blockIdx.y * TY;
    const int b  = blockIdx.z;
    const float* ub = u + b * IMG;

    for (int i = tid; i < LUTE; i += 512) slut[i] = g_lut[i];
    for (int i = tid; i < NF * 25; i += 512) sfilt[i] = filters[i];

    // load u with halo 4, zero-padded
    for (int i = tid; i < NUP; i += 512) {
        int uy = i / UW, ux = i - uy * UW;
        int gy = y0 + uy - 4, gx = x0 + ux - 4;
        float v = 0.0f;
        if (gy >= 0 && gy < HH && gx >= 0 && gx < WW) v = ub[gy * WW + gx];
        su[i] = v;
    }
    __syncthreads();

    // u_sigma on S-region (center of S point (sy,sx) is su[(sy+2)*UW + sx+2])
    for (int i = tid; i < NSP; i += 512) {
        int sy = i / SW, sx = i - sy * SW;
        const float* p = &su[(sy + 1) * UW + sx + 1];
        float s = 0.0f;
        #pragma unroll
        for (int dy = 0; dy < 3; dy++)
            #pragma unroll
            for (int dx = 0; dx < 3; dx++)
                s += p[dy * UW + dx];
        susig[i] = s * (1.0f / 9.0f);
    }
    __syncthreads();

    const float invM = g_invM[0];
    const int ty = tid >> 5, tx = tid & 31;   // 32x16 output mapping
    float acc = 0.0f;

    for (int k = 0; k < NF; k++) {
        float fk[25];
        #pragma unroll
        for (int r = 0; r < 25; r++) fk[r] = sfilt[k * 25 + r];

        // S = u_sigma * phi(conv_k(u)) on the S-region, 0 outside image
        for (int i = tid; i < NSP; i += 512) {
            int sy = i / SW, sx = i - sy * SW;
            const float* p = &su[sy * UW + sx];
            float c = 0.0f;
            #pragma unroll
            for (int ry = 0; ry < 5; ry++)
                #pragma unroll
                for (int rx = 0; rx < 5; rx++)
                    c += fk[ry * 5 + rx] * p[ry * UW + rx];
            // LUT lookup with linear interpolation
            float xc = fminf(fmaxf(c, XMIN), 2.0f);
            float t = (xc - XMIN) * LUT_SCALE;
            int idx = (int)t;
            idx = idx > (LUTN - 1) ? (LUTN - 1) : idx;
            float fr = t - (float)idx;
            float l0 = slut[idx];
            float phi = l0 + fr * (slut[idx + 1] - l0);
            float val = susig[i] * phi;
            int iy = y0 + sy - 2, ix = x0 + sx - 2;
            if (iy < 0 || iy >= HH || ix < 0 || ix >= WW) val = 0.0f;
            sS[i] = val;
        }
        __syncthreads();

        // transposed conv accumulation (true convolution with original k)
        {
            const float* pS = &sS[(ty + 4) * SW + tx + 4];
            #pragma unroll
            for (int ry = 0; ry < 5; ry++)
                #pragma unroll
                for (int rx = 0; rx < 5; rx++)
                    acc += fk[ry * 5 + rx] * pS[-ry * SW - rx];
        }
        __syncthreads();
    }

    int iy = y0 + ty, ix = x0 + tx;
    if (iy < HH && ix < WW) {
        float uv = su[(ty + 4) * UW + tx + 4];
        float fv = f[b * IMG + iy * WW + ix];
        float lam = lam_p[0];
        float reac = lam * (uv - fv) / (uv * uv + 1e-3f);
        float o = uv - acc * invM - reac;
        out[b * IMG + iy * WW + ix] = fminf(fmaxf(o, 0.0f), 1.0f);
    }
}

// ------------------------------------------------------------------- launch
extern "C" void kernel_launch(void* const* d_in, const int* in_sizes, int n_in,
                              void* d_out, int out_size) {
    const float* u       = (const float*)d_in[0];
    const float* f       = (const float*)d_in[1];
    const float* filters = (const float*)d_in[2];
    const float* lam     = (const float*)d_in[3];
    const float* mu      = (const float*)d_in[4];
    const float* w       = (const float*)d_in[5];
    float* out = (float*)d_out;

    lut_kernel<<<(LUTE + 255) / 256, 256>>>(mu, w);
    red1_kernel<<<256, 256>>>(u);
    red2_kernel<<<1, 256>>>();
    dim3 grid((WW + TX - 1) / TX, (HH + TY - 1) / TY, BB);
    tnrd_kernel<<<grid, 512>>>(u, f, filters, lam, out);
}

// round 2
// speedup vs baseline: 1.8257x; 1.8257x over previous
#include <cuda_runtime.h>

#define HH 180
#define WW 180
#define BB 8
#define NF 24
#define IMG (HH*WW)            // 32400
#define TOT (BB*IMG)           // 259200

#define TX 60
#define TY 12
#define SH (TY+4)              // 16 S-region rows
#define SWL 64                 // S-region logical width (TX+4)
#define SWP 68                 // padded S width (bank shift 4/row)
#define UW 68                  // u-region width (TX+8), %4==0
#define UH (TY+8)              // 20
#define NUP (UW*UH)            // 1360

#define LUTN 4096
#define XMIN (-2.0f)
#define LUT_SCALE 1024.0f      // LUTN/4

__device__ float2 g_lut2[LUTN];
__device__ float  g_part[256];
__device__ float  g_invM[1];

// ---------------------------------------------------------------- LUT build
// g_lut2[i] = (phi(x_i), phi(x_{i+1}))  for linear interp with one LDS.64
__global__ void lut_kernel(const float* __restrict__ mu,
                           const float* __restrict__ w) {
    int i = blockIdx.x * blockDim.x + threadIdx.x;
    if (i <= LUTN) {
        float x = XMIN + (float)i * (4.0f / (float)LUTN);
        float s = 0.0f;
        #pragma unroll 1
        for (int j = 0; j < 31; j++) {
            float d = x - mu[j];
            s += w[j] * expf(-d * d * 50.0f);   // 1/(2*0.1^2) = 50
        }
        if (i < LUTN) g_lut2[i].x = s;
        if (i > 0)    g_lut2[i - 1].y = s;
    }
}

// ------------------------------------------------- deterministic M reduction
// sum(u_sigma) = sum_q u[q] * cy(q)*cx(q) / 9   (count_include_pad avg pool)
__global__ void red1_kernel(const float* __restrict__ u) {
    __shared__ float red[256];
    int tid = threadIdx.x;
    float s = 0.0f;
    for (int i = blockIdx.x * 256 + tid; i < TOT; i += 256 * 256) {
        int pix = i % IMG;
        int y = pix / WW;
        int x = pix - y * WW;
        float cy = (y == 0 || y == HH - 1) ? 2.0f : 3.0f;
        float cx = (x == 0 || x == WW - 1) ? 2.0f : 3.0f;
        s += u[i] * (cy * cx);
    }
    red[tid] = s;
    __syncthreads();
    #pragma unroll
    for (int st = 128; st > 0; st >>= 1) {
        if (tid < st) red[tid] += red[tid + st];
        __syncthreads();
    }
    if (tid == 0) g_part[blockIdx.x] = red[0];
}

__global__ void red2_kernel() {
    __shared__ float red[256];
    int tid = threadIdx.x;
    red[tid] = g_part[tid];
    __syncthreads();
    #pragma unroll
    for (int st = 128; st > 0; st >>= 1) {
        if (tid < st) red[tid] += red[tid + st];
        __syncthreads();
    }
    if (tid == 0) {
        float M = red[0] / (9.0f * (float)TOT) + 0.001f;
        g_invM[0] = 1.0f / M;
    }
}

// ----------------------------------------------------------- fused main pass
__global__ __launch_bounds__(256, 2)
void tnrd_kernel(const float* __restrict__ u,
                 const float* __restrict__ f,
                 const float* __restrict__ filters,
                 const float* __restrict__ lam_p,
                 float* __restrict__ out) {
    __shared__ float  su[UH * UW];      // u with halo-4       (5440 B)
    __shared__ float  sS[SH * SWP];     // scaled_phi staging  (4352 B)
    __shared__ float2 slut[LUTN];       //                     (32768 B)
    __shared__ float  sfilt[NF * 28];   // filters, stride 28  (2688 B)

    const int tid = threadIdx.x;
    const int x0 = blockIdx.x * TX;
    const int y0 = blockIdx.y * TY;
    const int b  = blockIdx.z;
    const float* ub = u + b * IMG;

    // cooperative loads
    {
        const float4* gl = (const float4*)g_lut2;   // 2048 float4
        float4* sl = (float4*)slut;
        for (int i = tid; i < LUTN / 2; i += 256) sl[i] = gl[i];
    }
    for (int i = tid; i < NF * 28; i += 256) {
        int k = i / 28, r = i - k * 28;
        sfilt[i] = (r < 25) ? filters[k * 25 + r] : 0.0f;
    }
    for (int i = tid; i < NUP; i += 256) {
        int uy = i / UW, ux = i - uy * UW;
        int gy = y0 + uy - 4, gx = x0 + ux - 4;
        float v = 0.0f;
        if (gy >= 0 && gy < HH && gx >= 0 && gx < WW) v = ub[gy * WW + gx];
        su[i] = v;
    }
    __syncthreads();

    // ---- per-thread S-strip: sy in 0..15, 4 consecutive x at sxq ----
    const int sy  = tid >> 4;
    const int sxq = (tid & 15) << 2;

    // register-resident 5x8 u window (constant across all k)
    float sur[5][8];
    #pragma unroll
    for (int r = 0; r < 5; r++) {
        float4 a = *(const float4*)&su[(sy + r) * UW + sxq];
        float4 c = *(const float4*)&su[(sy + r) * UW + sxq + 4];
        sur[r][0] = a.x; sur[r][1] = a.y; sur[r][2] = a.z; sur[r][3] = a.w;
        sur[r][4] = c.x; sur[r][5] = c.y; sur[r][6] = c.z; sur[r][7] = c.w;
    }

    // u_sigma for the 4 S-points, premultiplied by border mask
    float susigm[4];
    {
        float colsum[6];
        #pragma unroll
        for (int c = 0; c < 6; c++)
            colsum[c] = sur[1][c + 1] + sur[2][c + 1] + sur[3][c + 1];
        #pragma unroll
        for (int j = 0; j < 4; j++) {
            float s = (colsum[j] + colsum[j + 1] + colsum[j + 2]) * (1.0f / 9.0f);
            int iy = y0 + sy - 2, ix = x0 + sxq + j - 2;
            if (iy < 0 || iy >= HH || ix < 0 || ix >= WW) s = 0.0f;
            susigm[j] = s;
        }
    }

    // output strip mapping (180 strips over 256 threads)
    const int oy  = tid / 15;
    const int oxq = (tid - oy * 15) * 4;
    const bool has_out = (tid < 180);

    float acc[4] = {0.0f, 0.0f, 0.0f, 0.0f};

    for (int k = 0; k < NF; k++) {
        // broadcast filter into registers (7 LDS.128)
        float fk[28];
        #pragma unroll
        for (int q = 0; q < 7; q++)
            *(float4*)&fk[4 * q] = *(const float4*)&sfilt[k * 28 + 4 * q];

        // conv from registers: 100 FFMA
        float cv[4] = {0.0f, 0.0f, 0.0f, 0.0f};
        #pragma unroll
        for (int ry = 0; ry < 5; ry++)
            #pragma unroll
            for (int rx = 0; rx < 5; rx++) {
                float fv = fk[ry * 5 + rx];
                #pragma unroll
                for (int j = 0; j < 4; j++)
                    cv[j] += fv * sur[ry][j + rx];
            }

        // LUT phi + scale, pack, store strip
        float4 v;
        #pragma unroll
        for (int j = 0; j < 4; j++) {
            float xc = fminf(fmaxf(cv[j], XMIN), 2.0f);
            float t = (xc - XMIN) * LUT_SCALE;
            int idx = (int)t;
            idx = idx > (LUTN - 1) ? (LUTN - 1) : idx;
            float fr = t - (float)idx;
            float2 L = slut[idx];
            float phi = L.x + fr * (L.y - L.x);
            float val = susigm[j] * phi;
            ((float*)&v)[j] = val;
        }
        *(float4*)&sS[sy * SWP + sxq] = v;
        __syncthreads();

        // transposed conv (row-streamed): 10 LDS.128 + 100 FFMA
        if (has_out) {
            #pragma unroll
            for (int rr = 0; rr < 5; rr++) {
                float tr[8];
                float4 a = *(const float4*)&sS[(oy + rr) * SWP + oxq];
                float4 c = *(const float4*)&sS[(oy + rr) * SWP + oxq + 4];
                tr[0] = a.x; tr[1] = a.y; tr[2] = a.z; tr[3] = a.w;
                tr[4] = c.x; tr[5] = c.y; tr[6] = c.z; tr[7] = c.w;
                #pragma unroll
                for (int rx = 0; rx < 5; rx++) {
                    float fv = fk[(4 - rr) * 5 + rx];
                    #pragma unroll
                    for (int j = 0; j < 4; j++)
                        acc[j] += fv * tr[j + 4 - rx];
                }
            }
        }
        __syncthreads();
    }

    if (has_out) {
        const float invM = g_invM[0];
        const float lam  = lam_p[0];
        int iy = y0 + oy, ixb = x0 + oxq;
        float4 fv4 = *(const float4*)&f[b * IMG + iy * WW + ixb];
        float4 o4;
        #pragma unroll
        for (int j = 0; j < 4; j++) {
            float uv = su[(oy + 4) * UW + oxq + 4 + j];
            float fv = ((const float*)&fv4)[j];
            float reac = lam * (uv - fv) / (uv * uv + 1e-3f);
            float o = uv - acc[j] * invM - reac;
            ((float*)&o4)[j] = fminf(fmaxf(o, 0.0f), 1.0f);
        }
        *(float4*)&out[b * IMG + iy * WW + ixb] = o4;
    }
}

// ------------------------------------------------------------------- launch
extern "C" void kernel_launch(void* const* d_in, const int* in_sizes, int n_in,
                              void* d_out, int out_size) {
    const float* u       = (const float*)d_in[0];
    const float* f       = (const float*)d_in[1];
    const float* filters = (const float*)d_in[2];
    const float* lam     = (const float*)d_in[3];
    const float* mu      = (const float*)d_in[4];
    const float* w       = (const float*)d_in[5];
    float* out = (float*)d_out;

    lut_kernel<<<(LUTN + 256) / 256, 256>>>(mu, w);
    red1_kernel<<<256, 256>>>(u);
    red2_kernel<<<1, 256>>>();
    dim3 grid(WW / TX, HH / TY, BB);   // 3 x 15 x 8 = 360 blocks
    tnrd_kernel<<<grid, 256>>>(u, f, filters, lam, out);
}

// round 4
// speedup vs baseline: 2.4462x; 1.3398x over previous
#include <cuda_runtime.h>

#define HH 180
#define WW 180
#define BB 8
#define NF 24
#define IMG (HH*WW)            // 32400
#define TOT (BB*IMG)           // 259200

#define TX 60
#define TY 12
#define SH (TY+4)              // 16 S-region rows
#define SWP 68                 // padded S width
#define UW 68                  // u-region width (TX+8)
#define UH (TY+8)              // 20
#define NUP (UW*UH)            // 1360
#define NSB (SH*SWP)           // 1088 floats per S buffer

#define LUTN 2048
#define XMIN (-2.0f)
#define LUT_SCALE 512.0f       // LUTN/4

__device__ float2 g_lut2[LUTN];
__device__ float  g_part[256];
__device__ float  g_invM[1];

// ---------------------------------------------------------------- LUT build
__global__ void lut_kernel(const float* __restrict__ mu,
                           const float* __restrict__ w) {
    int i = blockIdx.x * blockDim.x + threadIdx.x;
    if (i <= LUTN) {
        float x = XMIN + (float)i * (4.0f / (float)LUTN);
        float s = 0.0f;
        #pragma unroll 1
        for (int j = 0; j < 31; j++) {
            float d = x - mu[j];
            s += w[j] * expf(-d * d * 50.0f);   // 1/(2*0.1^2) = 50
        }
        if (i < LUTN) g_lut2[i].x = s;
        if (i > 0)    g_lut2[i - 1].y = s;
    }
}

// ------------------------------------------------- deterministic M reduction
__global__ void red1_kernel(const float* __restrict__ u) {
    __shared__ float red[256];
    int tid = threadIdx.x;
    float s = 0.0f;
    for (int i = blockIdx.x * 256 + tid; i < TOT; i += 256 * 256) {
        int pix = i % IMG;
        int y = pix / WW;
        int x = pix - y * WW;
        float cy = (y == 0 || y == HH - 1) ? 2.0f : 3.0f;
        float cx = (x == 0 || x == WW - 1) ? 2.0f : 3.0f;
        s += u[i] * (cy * cx);
    }
    red[tid] = s;
    __syncthreads();
    #pragma unroll
    for (int st = 128; st > 0; st >>= 1) {
        if (tid < st) red[tid] += red[tid + st];
        __syncthreads();
    }
    if (tid == 0) g_part[blockIdx.x] = red[0];
}

__global__ void red2_kernel() {
    __shared__ float red[256];
    int tid = threadIdx.x;
    red[tid] = g_part[tid];
    __syncthreads();
    #pragma unroll
    for (int st = 128; st > 0; st >>= 1) {
        if (tid < st) red[tid] += red[tid + st];
        __syncthreads();
    }
    if (tid == 0) {
        float M = red[0] * (1.0f / (9.0f * (float)TOT)) + 0.001f;
        g_invM[0] = 1.0f / M;
    }
}

// ----------------------------------------------------------- fused main pass
__global__ __launch_bounds__(256, 3)
void tnrd_kernel(const float* __restrict__ u,
                 const float* __restrict__ f,
                 const float* __restrict__ filters,
                 const float* __restrict__ lam_p,
                 float* __restrict__ out) {
    __shared__ float  su[NUP];             // u with halo-4        (5440 B)
    __shared__ float  sS[4][NSB];          // 4 scaled_phi buffers (17408 B)
    __shared__ float2 slut[LUTN];          //                      (16384 B)
    __shared__ float  sfiltR[NF * 5 * 8];  // row-padded filters   (3840 B)

    const int tid = threadIdx.x;
    const int x0 = blockIdx.x * TX;
    const int y0 = blockIdx.y * TY;
    const int b  = blockIdx.z;
    const float* ub = u + b * IMG;

    // cooperative loads
    {
        const float4* gl = (const float4*)g_lut2;   // 1024 float4
        float4* sl = (float4*)slut;
        for (int i = tid; i < LUTN / 2; i += 256) sl[i] = gl[i];
    }
    for (int i = tid; i < NF * 5 * 8; i += 256) {
        int kr = i >> 3, x = i & 7;       // kr = k*5+row
        sfiltR[i] = (x < 5) ? filters[kr * 5 + x] : 0.0f;
    }
    for (int i = tid; i < NUP; i += 256) {
        int uy = i / UW, ux = i - uy * UW;
        int gy = y0 + uy - 4, gx = x0 + ux - 4;
        float v = 0.0f;
        if (gy >= 0 && gy < HH && gx >= 0 && gx < WW) v = ub[gy * WW + gx];
        su[i] = v;
    }
    __syncthreads();

    // ---- per-thread S-strip: sy in 0..15, 4 consecutive x at sxq ----
    const int sy  = tid >> 4;
    const int sxq = (tid & 15) << 2;

    // register-resident 5x8 u window (constant across all k)
    float sur[5][8];
    #pragma unroll
    for (int r = 0; r < 5; r++) {
        float4 a = *(const float4*)&su[(sy + r) * UW + sxq];
        float4 c = *(const float4*)&su[(sy + r) * UW + sxq + 4];
        sur[r][0] = a.x; sur[r][1] = a.y; sur[r][2] = a.z; sur[r][3] = a.w;
        sur[r][4] = c.x; sur[r][5] = c.y; sur[r][6] = c.z; sur[r][7] = c.w;
    }

    // u_sigma for the 4 S-points, premultiplied by border mask
    float susigm[4];
    {
        float colsum[6];
        #pragma unroll
        for (int c = 0; c < 6; c++)
            colsum[c] = sur[1][c + 1] + sur[2][c + 1] + sur[3][c + 1];
        #pragma unroll
        for (int j = 0; j < 4; j++) {
            float s = (colsum[j] + colsum[j + 1] + colsum[j + 2]) * (1.0f / 9.0f);
            int iy = y0 + sy - 2, ix = x0 + sxq + j - 2;
            if (iy < 0 || iy >= HH || ix < 0 || ix >= WW) s = 0.0f;
            susigm[j] = s;
        }
    }

    // output strip mapping (180 strips over 256 threads)
    const int oy  = tid / 15;
    const int oxq = (tid - oy * 15) * 4;
    const bool has_out = (tid < 180);

    float acc[4] = {0.0f, 0.0f, 0.0f, 0.0f};

    #pragma unroll 1
    for (int p = 0; p < NF / 2; p++) {
        const int bb = (p & 1) << 1;      // buffer base: 0 or 2

        // phase 1: conv + LUT for filters 2p and 2p+1
        #pragma unroll
        for (int kk = 0; kk < 2; kk++) {
            const int k = 2 * p + kk;
            float cv[4] = {0.0f, 0.0f, 0.0f, 0.0f};
            #pragma unroll
            for (int ry = 0; ry < 5; ry++) {
                const float* fr = &sfiltR[(k * 5 + ry) * 8];
                float4 fa = *(const float4*)fr;
                float  fe = fr[4];
                float fv;
                #pragma unroll
                for (int rx = 0; rx < 5; rx++) {
                    fv = (rx == 0) ? fa.x : (rx == 1) ? fa.y : (rx == 2) ? fa.z
                       : (rx == 3) ? fa.w : fe;
                    #pragma unroll
                    for (int j = 0; j < 4; j++)
                        cv[j] += fv * sur[ry][j + rx];
                }
            }
            float4 v;
            #pragma unroll
            for (int j = 0; j < 4; j++) {
                float xc = fminf(fmaxf(cv[j], XMIN), 2.0f);
                float t = (xc - XMIN) * LUT_SCALE;
                int idx = (int)t;
                idx = idx > (LUTN - 1) ? (LUTN - 1) : idx;
                float frac = t - (float)idx;
                float2 L = slut[idx];
                float phi = L.x + frac * (L.y - L.x);
                ((float*)&v)[j] = susigm[j] * phi;
            }
            *(float4*)&sS[bb + kk][sy * SWP + sxq] = v;
        }
        __syncthreads();

        // phase 2: transposed conv for both filters of the pair
        if (has_out) {
            #pragma unroll
            for (int kk = 0; kk < 2; kk++) {
                const int k = 2 * p + kk;
                const float* Sb = sS[bb + kk];
                #pragma unroll
                for (int rr = 0; rr < 5; rr++) {
                    float tr[8];
                    float4 a = *(const float4*)&Sb[(oy + rr) * SWP + oxq];
                    float4 c = *(const float4*)&Sb[(oy + rr) * SWP + oxq + 4];
                    tr[0] = a.x; tr[1] = a.y; tr[2] = a.z; tr[3] = a.w;
                    tr[4] = c.x; tr[5] = c.y; tr[6] = c.z; tr[7] = c.w;
                    const float* fr = &sfiltR[(k * 5 + (4 - rr)) * 8];
                    float4 fa = *(const float4*)fr;
                    float  fe = fr[4];
                    float fv;
                    #pragma unroll
                    for (int rx = 0; rx < 5; rx++) {
                        fv = (rx == 0) ? fa.x : (rx == 1) ? fa.y : (rx == 2) ? fa.z
                           : (rx == 3) ? fa.w : fe;
                        #pragma unroll
                        for (int j = 0; j < 4; j++)
                            acc[j] += fv * tr[j + 4 - rx];
                    }
                }
            }
        }
    }

    if (has_out) {
        const float invM = g_invM[0];
        const float lam  = lam_p[0];
        int iy = y0 + oy, ixb = x0 + oxq;
        float4 fv4 = *(const float4*)&f[b * IMG + iy * WW + ixb];
        float4 uv4 = *(const float4*)&su[(oy + 4) * UW + oxq + 4];
        float4 o4;
        #pragma unroll
        for (int j = 0; j < 4; j++) {
            float uv = ((const float*)&uv4)[j];
            float fv = ((const float*)&fv4)[j];
            float reac = lam * (uv - fv) / (uv * uv + 1e-3f);
            float o = uv - acc[j] * invM - reac;
            ((float*)&o4)[j] = fminf(fmaxf(o, 0.0f), 1.0f);
        }
        *(float4*)&out[b * IMG + iy * WW + ixb] = o4;
    }
}

// ------------------------------------------------------------------- launch
extern "C" void kernel_launch(void* const* d_in, const int* in_sizes, int n_in,
                              void* d_out, int out_size) {
    const float* u       = (const float*)d_in[0];
    const float* f       = (const float*)d_in[1];
    const float* filters = (const float*)d_in[2];
    const float* lam     = (const float*)d_in[3];
    const float* mu      = (const float*)d_in[4];
    const float* w       = (const float*)d_in[5];
    float* out = (float*)d_out;

    lut_kernel<<<(LUTN + 256) / 256, 256>>>(mu, w);
    red1_kernel<<<256, 256>>>(u);
    red2_kernel<<<1, 256>>>();
    dim3 grid(WW / TX, HH / TY, BB);   // 3 x 15 x 8 = 360 blocks
    tnrd_kernel<<<grid, 256>>>(u, f, filters, lam, out);
}

// round 5
// speedup vs baseline: 2.5366x; 1.0370x over previous
#include <cuda_runtime.h>

#define HH 180
#define WW 180
#define BB 8
#define NF 24
#define IMG (HH*WW)            // 32400
#define TOT (BB*IMG)           // 259200

#define TX 60
#define TY 12
#define SH (TY+4)              // 16 S-region rows
#define UW 68                  // u-region width (TX+8)
#define UH (TY+8)              // 20
#define NUP (UW*UH)            // 1360
#define PW 132                 // interleaved pair-buffer row width (2*64+4 pad)
#define NPB (SH*PW)            // 2112 floats per pair buffer

#define LUTN 2048
#define XMIN (-2.0f)
#define LUT_SCALE 512.0f       // LUTN/4
#define LUT_BLOCKS 9           // 9*256 = 2304 >= LUTN+1

__device__ float2 g_lut2[LUTN];
__device__ float  g_part[256];
__device__ float  g_invM[1];
__device__ int    g_ctr = 0;

typedef unsigned long long u64;
__device__ __forceinline__ u64 pack2(float lo, float hi) {
    u64 r; asm("mov.b64 %0,{%1,%2};" : "=l"(r) : "f"(lo), "f"(hi)); return r;
}
__device__ __forceinline__ float2 unpack2(u64 v) {
    float2 r; asm("mov.b64 {%0,%1},%2;" : "=f"(r.x), "=f"(r.y) : "l"(v)); return r;
}
__device__ __forceinline__ void fma2(u64 &d, u64 a, u64 b) {
    asm("fma.rn.f32x2 %0,%1,%2,%3;" : "=l"(d) : "l"(a), "l"(b), "l"(d));
}

// ---------------------------------------- fused prologue: LUT + M reduction
__global__ void pre_kernel(const float* __restrict__ u,
                           const float* __restrict__ mu,
                           const float* __restrict__ w) {
    int tid = threadIdx.x;
    if (blockIdx.x < LUT_BLOCKS) {
        int i = blockIdx.x * 256 + tid;
        if (i <= LUTN) {
            float x = XMIN + (float)i * (4.0f / (float)LUTN);
            float s = 0.0f;
            #pragma unroll 1
            for (int j = 0; j < 31; j++) {
                float d = x - mu[j];
                s += w[j] * expf(-d * d * 50.0f);   // 1/(2*0.1^2) = 50
            }
            if (i < LUTN) g_lut2[i].x = s;
            if (i > 0)    g_lut2[i - 1].y = s;
        }
        return;
    }
    // deterministic reduction: sum_q u[q]*cy*cx  (avg-pool closed form)
    __shared__ float red[256];
    __shared__ int sdone;
    int bid = blockIdx.x - LUT_BLOCKS;          // 0..255
    float s = 0.0f;
    for (int i = bid * 256 + tid; i < TOT; i += 256 * 256) {
        int pix = i % IMG;
        int y = pix / WW;
        int x = pix - y * WW;
        float cy = (y == 0 || y == HH - 1) ? 2.0f : 3.0f;
        float cx = (x == 0 || x == WW - 1) ? 2.0f : 3.0f;
        s += u[i] * (cy * cx);
    }
    red[tid] = s;
    __syncthreads();
    #pragma unroll
    for (int st = 128; st > 0; st >>= 1) {
        if (tid < st) red[tid] += red[tid + st];
        __syncthreads();
    }
    if (tid == 0) {
        g_part[bid] = red[0];
        __threadfence();
        int old = atomicAdd(&g_ctr, 1);
        sdone = (old == 255) ? 1 : 0;
    }
    __syncthreads();
    if (sdone) {
        __threadfence();
        red[tid] = g_part[tid];
        __syncthreads();
        #pragma unroll
        for (int st = 128; st > 0; st >>= 1) {
            if (tid < st) red[tid] += red[tid + st];
            __syncthreads();
        }
        if (tid == 0) {
            float M = red[0] * (1.0f / (9.0f * (float)TOT)) + 0.001f;
            g_invM[0] = 1.0f / M;
            g_ctr = 0;                           // reset for graph replay
        }
    }
}

// ----------------------------------------------------------- fused main pass
__global__ __launch_bounds__(256, 3)
void tnrd_kernel(const float* __restrict__ u,
                 const float* __restrict__ f,
                 const float* __restrict__ filters,
                 const float* __restrict__ lam_p,
                 float* __restrict__ out) {
    __shared__ float  su[NUP];            // u with halo-4          (5440 B)
    __shared__ float  sS[2][NPB];         // interleaved pair bufs  (16896 B)
    __shared__ float2 slut[LUTN];         //                        (16384 B)
    __shared__ float2 sfiltP[12 * 25];    // (fA,fB) per tap        (2400 B)

    const int tid = threadIdx.x;
    const int x0 = blockIdx.x * TX;
    const int y0 = blockIdx.y * TY;
    const int b  = blockIdx.z;
    const float* ub = u + b * IMG;

    // cooperative loads
    {
        const float4* gl = (const float4*)g_lut2;   // 1024 float4
        float4* sl = (float4*)slut;
        for (int i = tid; i < LUTN / 2; i += 256) sl[i] = gl[i];
    }
    for (int i = tid; i < 12 * 25; i += 256) {
        int p = i / 25, t = i - p * 25;
        float2 v;
        v.x = filters[(2 * p) * 25 + t];
        v.y = filters[(2 * p + 1) * 25 + t];
        sfiltP[i] = v;
    }
    for (int i = tid; i < NUP; i += 256) {
        int uy = i / UW, ux = i - uy * UW;
        int gy = y0 + uy - 4, gx = x0 + ux - 4;
        float v = 0.0f;
        if (gy >= 0 && gy < HH && gx >= 0 && gx < WW) v = ub[gy * WW + gx];
        su[i] = v;
    }
    __syncthreads();

    // ---- per-thread S-strip: sy in 0..15, 4 consecutive x at sxq ----
    const int sy  = tid >> 4;
    const int sxq = (tid & 15) << 2;

    // register-resident 5x8 u window (constant across all filters)
    float sur[5][8];
    #pragma unroll
    for (int r = 0; r < 5; r++) {
        float4 a = *(const float4*)&su[(sy + r) * UW + sxq];
        float4 c = *(const float4*)&su[(sy + r) * UW + sxq + 4];
        sur[r][0] = a.x; sur[r][1] = a.y; sur[r][2] = a.z; sur[r][3] = a.w;
        sur[r][4] = c.x; sur[r][5] = c.y; sur[r][6] = c.z; sur[r][7] = c.w;
    }

    // u_sigma for the 4 S-points, premultiplied by border mask
    float susigm[4];
    {
        float colsum[6];
        #pragma unroll
        for (int c = 0; c < 6; c++)
            colsum[c] = sur[1][c + 1] + sur[2][c + 1] + sur[3][c + 1];
        #pragma unroll
        for (int j = 0; j < 4; j++) {
            float s = (colsum[j] + colsum[j + 1] + colsum[j + 2]) * (1.0f / 9.0f);
            int iy = y0 + sy - 2, ix = x0 + sxq + j - 2;
            if (iy < 0 || iy >= HH || ix < 0 || ix >= WW) s = 0.0f;
            susigm[j] = s;
        }
    }

    // output strip mapping (180 strips over 256 threads)
    const int oy  = tid / 15;
    const int oxq = (tid - oy * 15) * 4;
    const bool has_out = (tid < 180);

    u64 accp[4] = {0ull, 0ull, 0ull, 0ull};   // packed (accA,accB)… summed at end

    #pragma unroll 1
    for (int p = 0; p < NF / 2; p++) {
        float* Sp = sS[p & 1];
        const u64* fp = (const u64*)&sfiltP[p * 25];

        // ---- phase 1: packed conv over the filter pair + LUT ----
        u64 cvp[4] = {0ull, 0ull, 0ull, 0ull};
        #pragma unroll
        for (int ry = 0; ry < 5; ry++) {
            u64 sp[8];
            #pragma unroll
            for (int x = 0; x < 8; x++) sp[x] = pack2(sur[ry][x], sur[ry][x]);
            #pragma unroll
            for (int rx = 0; rx < 5; rx++) {
                u64 F = fp[ry * 5 + rx];
                #pragma unroll
                for (int j = 0; j < 4; j++)
                    fma2(cvp[j], F, sp[j + rx]);
            }
        }
        float vA[4], vB[4];
        #pragma unroll
        for (int j = 0; j < 4; j++) {
            float2 c = unpack2(cvp[j]);
            #pragma unroll
            for (int kk = 0; kk < 2; kk++) {
                float cv = kk ? c.y : c.x;
                float xc = fminf(fmaxf(cv, XMIN), 2.0f);
                float t = fmaf(xc, LUT_SCALE, -XMIN * LUT_SCALE);
                int idx = (int)t;
                idx = idx > (LUTN - 1) ? (LUTN - 1) : idx;
                float frac = t - (float)idx;
                float2 L = slut[idx];
                float phi = L.x + frac * (L.y - L.x);
                float val = susigm[j] * phi;
                if (kk) vB[j] = val; else vA[j] = val;
            }
        }
        {
            float4 s0, s1;
            s0.x = vA[0]; s0.y = vB[0]; s0.z = vA[1]; s0.w = vB[1];
            s1.x = vA[2]; s1.y = vB[2]; s1.z = vA[3]; s1.w = vB[3];
            *(float4*)&Sp[sy * PW + sxq * 2]     = s0;
            *(float4*)&Sp[sy * PW + sxq * 2 + 4] = s1;
        }
        __syncthreads();

        // ---- phase 2: packed transposed conv (both filters at once) ----
        if (has_out) {
            #pragma unroll
            for (int rr = 0; rr < 5; rr++) {
                const ulonglong2* T =
                    (const ulonglong2*)&Sp[(oy + rr) * PW + oxq * 2];
                ulonglong2 q0 = T[0], q1 = T[1], q2 = T[2], q3 = T[3];
                u64 P[8] = {q0.x, q0.y, q1.x, q1.y, q2.x, q2.y, q3.x, q3.y};
                #pragma unroll
                for (int rx = 0; rx < 5; rx++) {
                    u64 F = fp[(4 - rr) * 5 + rx];
                    #pragma unroll
                    for (int j = 0; j < 4; j++)
                        fma2(accp[j], F, P[j + 4 - rx]);
                }
            }
        }
    }

    if (has_out) {
        const float invM = g_invM[0];
        const float lam  = lam_p[0];
        int iy = y0 + oy, ixb = x0 + oxq;
        float4 fv4 = *(const float4*)&f[b * IMG + iy * WW + ixb];
        float4 uv4 = *(const float4*)&su[(oy + 4) * UW + oxq + 4];
        float4 o4;
        #pragma unroll
        for (int j = 0; j < 4; j++) {
            float2 a = unpack2(accp[j]);
            float acc = a.x + a.y;
            float uv = ((const float*)&uv4)[j];
            float fv = ((const float*)&fv4)[j];
            float reac = lam * (uv - fv) / (uv * uv + 1e-3f);
            float o = uv - acc * invM - reac;
            ((float*)&o4)[j] = fminf(fmaxf(o, 0.0f), 1.0f);
        }
        *(float4*)&out[b * IMG + iy * WW + ixb] = o4;
    }
}

// ------------------------------------------------------------------- launch
extern "C" void kernel_launch(void* const* d_in, const int* in_sizes, int n_in,
                              void* d_out, int out_size) {
    const float* u       = (const float*)d_in[0];
    const float* f       = (const float*)d_in[1];
    const float* filters = (const float*)d_in[2];
    const float* lam     = (const float*)d_in[3];
    const float* mu      = (const float*)d_in[4];
    const float* w       = (const float*)d_in[5];
    float* out = (float*)d_out;

    pre_kernel<<<LUT_BLOCKS + 256, 256>>>(u, mu, w);
    dim3 grid(WW / TX, HH / TY, BB);   // 3 x 15 x 8 = 360 blocks
    tnrd_kernel<<<grid, 256>>>(u, f, filters, lam, out);
}